// round 2
// baseline (speedup 1.0000x reference)
#include <cuda_runtime.h>
#include <cstdint>
#include <math.h>

// Problem constants (fixed shapes for this problem instance)
#define NTOK 8192          // B*S = 2*4096 tokens
#define DDIM 1024          // model dim
#define FDIM 4096          // ffn dim
#define NEXP 4             // only experts 0..3 are referenced by the source loop
#define KCAT (NEXP*FDIM)   // 16384 : concatenated K for the second GEMM

// ---------------------------------------------------------------------------
// Scratch (static device globals; allocation inside kernel_launch is banned)
// ---------------------------------------------------------------------------
__device__ float g_W1eff[(size_t)NEXP*DDIM*FDIM];   //  67 MB  W1[e] + A1[e]@B1[e], tf32-rounded
__device__ float g_W2eff[(size_t)NEXP*FDIM*DDIM];   //  67 MB  stacked [e*F+f][d], tf32-rounded
__device__ float g_Hcat [(size_t)NTOK*KCAT];        // 536 MB  w_e * gelu(x@W1eff_e), tf32-rounded
__device__ float g_Xtf  [(size_t)NTOK*DDIM];        //  33 MB  tf32-rounded activations
__device__ float g_w    [NTOK*4];                   // routing weights for experts 0..3

// ---------------------------------------------------------------------------
// Helpers
// ---------------------------------------------------------------------------
__device__ __forceinline__ uint32_t f2tf32(float f) {
  uint32_t r; asm("cvt.rna.tf32.f32 %0, %1;" : "=r"(r) : "f"(f)); return r;
}
__device__ __forceinline__ float gelu_tanh(float x) {
  // matches jax.nn.gelu(approximate=True)
  float c = x + 0.044715f * x * x * x;
  return 0.5f * x * (1.0f + tanhf(0.7978845608028654f * c));
}

#define CPASYNC16(dst_u32, src_ptr) \
  asm volatile("cp.async.cg.shared.global [%0], [%1], 16;\n" :: "r"(dst_u32), "l"(src_ptr))

// ---------------------------------------------------------------------------
// Fold kernel:  out[e][row][col] = rna_tf32( W[e][row][col] + sum_r A[e][row][r]*B[e][r][col] )
// Used for both W1eff (rows=D, cols=F) and W2eff (rows=F, cols=D).
// NOTE: W/A/B hold 16 experts; we index only e<4. Rank R=16 fixed.
// ---------------------------------------------------------------------------
__global__ void fold_kernel(const float* __restrict__ W, const float* __restrict__ A,
                            const float* __restrict__ Bm, float* __restrict__ out,
                            int rows, int cols) {
  int bid = blockIdx.x;
  int e = bid / rows, r0 = bid - e * rows;
  const float* a = A + ((size_t)e * rows + r0) * 16;
  float ar[16];
#pragma unroll
  for (int r = 0; r < 16; r++) ar[r] = a[r];
  const float* w  = W  + ((size_t)e * rows + r0) * cols;
  const float* bm = Bm + (size_t)e * 16 * cols;
  float* o = out + ((size_t)e * rows + r0) * cols;
  for (int c = threadIdx.x * 4; c < cols; c += 256 * 4) {
    float4 acc = *(const float4*)(w + c);
#pragma unroll
    for (int r = 0; r < 16; r++) {
      float4 b = *(const float4*)(bm + (size_t)r * cols + c);
      acc.x += ar[r] * b.x; acc.y += ar[r] * b.y;
      acc.z += ar[r] * b.z; acc.w += ar[r] * b.w;
    }
    float4 ov;
    ov.x = __uint_as_float(f2tf32(acc.x));
    ov.y = __uint_as_float(f2tf32(acc.y));
    ov.z = __uint_as_float(f2tf32(acc.z));
    ov.w = __uint_as_float(f2tf32(acc.w));
    *(float4*)(o + c) = ov;
  }
}

// ---------------------------------------------------------------------------
// tf32 round of activations
// ---------------------------------------------------------------------------
__global__ void convert_kernel(const float* __restrict__ x, float* __restrict__ o) {
  size_t i = ((size_t)blockIdx.x * 256 + threadIdx.x) * 4;
  float4 v = *(const float4*)(x + i);
  v.x = __uint_as_float(f2tf32(v.x));
  v.y = __uint_as_float(f2tf32(v.y));
  v.z = __uint_as_float(f2tf32(v.z));
  v.w = __uint_as_float(f2tf32(v.w));
  *(float4*)(o + i) = v;
}

// ---------------------------------------------------------------------------
// Gating: one warp per token. Full fp32 (selection must match the reference!).
// w_out[i] = exp(l_i - max) * [i in top4] / sum_{j in top4} exp(l_j - max), i<4
// (the softmax denominator cancels in the renormalized ratio)
// ---------------------------------------------------------------------------
__global__ void gate_kernel(const float* __restrict__ x, const float* __restrict__ Wg,
                            float* __restrict__ wout) {
  int token = (blockIdx.x * blockDim.x + threadIdx.x) >> 5;
  int lane = threadIdx.x & 31;
  if (token >= NTOK) return;
  const float* xr = x + (size_t)token * DDIM;
  float l[16];
#pragma unroll
  for (int e = 0; e < 16; e++) l[e] = 0.f;
  for (int d = lane; d < DDIM; d += 32) {
    float xv = xr[d];
    const float* wr = Wg + (size_t)d * 16;
#pragma unroll
    for (int e = 0; e < 16; e++) l[e] += xv * wr[e];
  }
#pragma unroll
  for (int e = 0; e < 16; e++)
#pragma unroll
    for (int off = 16; off; off >>= 1) l[e] += __shfl_xor_sync(0xFFFFFFFFu, l[e], off);
  if (lane == 0) {
    float mx = l[0];
#pragma unroll
    for (int e = 1; e < 16; e++) mx = fmaxf(mx, l[e]);
    float p[16];
#pragma unroll
    for (int e = 0; e < 16; e++) p[e] = expf(l[e] - mx);
    bool sel[16];
#pragma unroll
    for (int e = 0; e < 16; e++) sel[e] = false;
    float ssum = 0.f;
    for (int j = 0; j < 4; j++) {           // argmax on logits; strict '>' keeps lower index on ties
      int bi = 0; float bv = -3.0e38f;
      for (int e = 0; e < 16; e++)
        if (!sel[e] && l[e] > bv) { bv = l[e]; bi = e; }
      sel[bi] = true; ssum += p[bi];
    }
    float inv = 1.f / ssum;
    for (int i = 0; i < 4; i++) wout[token * 4 + i] = sel[i] ? p[i] * inv : 0.f;
  }
}

// ---------------------------------------------------------------------------
// tf32 GEMM: C[M,N] = A[M,K](row-major) @ B[K,N](row-major)
//   tiles: BM=128 BN=128 BK=32, 256 threads = 8 warps (2x4), warp tile 64x32
//   mma.sync.aligned.m16n8k8.row.col.f32.tf32.tf32.f32, cp.async double buffer
//   EPI==0: plain fp32 store.
//   EPI==1: C = rna_tf32( gelu(acc) * w[row][expert] )  (MoE hidden, pre-scaled)
// All dims divisible by tile sizes for this problem -> no bounds checks.
// ---------------------------------------------------------------------------
#define SA_STRIDE 36              // 32 + 4 pad (conflict-free A-frag LDS)
#define SB_STRIDE 136             // 128 + 8 pad (conflict-free B-frag LDS)
#define SA_STAGE (128*SA_STRIDE)  // 4608 floats
#define SB_STAGE (32*SB_STRIDE)   // 4352 floats
#define GEMM_SMEM_BYTES ((2*SA_STAGE + 2*SB_STAGE)*4)  // 71680

template <int EPI>
__global__ void __launch_bounds__(256, 2)
gemm_tf32(const float* __restrict__ A, const float* __restrict__ Bbase,
          float* __restrict__ Cbase, const float* __restrict__ wgt,
          int K, int lda, int ldb, int ldc, long Bstride, long Cstride) {
  extern __shared__ float smem[];
  float* sA = smem;
  float* sB = smem + 2 * SA_STAGE;
  const int tid = threadIdx.x;
  const int lane = tid & 31, wid = tid >> 5;
  const int wm = wid >> 2, wn = wid & 3;     // warp grid 2(m) x 4(n)
  const int g = lane >> 2, t = lane & 3;
  const int e = blockIdx.z;
  const float* Bp = Bbase + (size_t)e * Bstride;
  float* Cp = Cbase + (size_t)e * Cstride;
  const int rowBase = blockIdx.y * 128;
  const int colBase = blockIdx.x * 128;

  const uint32_t sAu = (uint32_t)__cvta_generic_to_shared(sA);
  const uint32_t sBu = (uint32_t)__cvta_generic_to_shared(sB);

  const int ar = tid >> 3, ac = (tid & 7) * 4;   // A staging: 32 rows/pass x 8 f4
  const int br = tid >> 5, bc = (tid & 31) * 4;  // B staging:  8 rows/pass x 32 f4

  float acc[4][4][4];
#pragma unroll
  for (int i = 0; i < 4; i++)
#pragma unroll
    for (int j = 0; j < 4; j++)
#pragma unroll
      for (int k = 0; k < 4; k++) acc[i][j][k] = 0.f;

  const int KT = K >> 5;

  // --- staging helpers ---
  auto loadA = [&](int s, int kt) {
    const float* base = A + (size_t)rowBase * lda + kt * 32;
#pragma unroll
    for (int i = 0; i < 4; i++) {
      int r = ar + i * 32;
      CPASYNC16(sAu + (uint32_t)((s * SA_STAGE + r * SA_STRIDE + ac) * 4),
                base + (size_t)r * lda + ac);
    }
  };
  auto loadB = [&](int s, int kt) {
    const float* base = Bp + (size_t)(kt * 32) * ldb + colBase;
#pragma unroll
    for (int i = 0; i < 4; i++) {
      int r = br + i * 8;
      CPASYNC16(sBu + (uint32_t)((s * SB_STAGE + r * SB_STRIDE + bc) * 4),
                base + (size_t)r * ldb + bc);
    }
  };

  loadA(0, 0); loadB(0, 0);
  asm volatile("cp.async.commit_group;\n");

  for (int kt = 0; kt < KT; ++kt) {
    int s = kt & 1;
    if (kt + 1 < KT) {
      loadA(s ^ 1, kt + 1); loadB(s ^ 1, kt + 1);
      asm volatile("cp.async.commit_group;\n");
      asm volatile("cp.async.wait_group 1;\n");
    } else {
      asm volatile("cp.async.wait_group 0;\n");
    }
    __syncthreads();
    const float* cA = sA + s * SA_STAGE;
    const float* cB = sB + s * SB_STAGE;
#pragma unroll
    for (int kk = 0; kk < 4; kk++) {
      uint32_t af[4][4], bf[4][2];
#pragma unroll
      for (int mi = 0; mi < 4; mi++) {
        const float* p = cA + (wm * 64 + mi * 16 + g) * SA_STRIDE + kk * 8 + t;
        af[mi][0] = __float_as_uint(p[0]);
        af[mi][1] = __float_as_uint(p[8 * SA_STRIDE]);
        af[mi][2] = __float_as_uint(p[4]);
        af[mi][3] = __float_as_uint(p[8 * SA_STRIDE + 4]);
      }
#pragma unroll
      for (int ni = 0; ni < 4; ni++) {
        const float* p = cB + (kk * 8 + t) * SB_STRIDE + wn * 32 + ni * 8 + g;
        bf[ni][0] = __float_as_uint(p[0]);
        bf[ni][1] = __float_as_uint(p[4 * SB_STRIDE]);
      }
#pragma unroll
      for (int mi = 0; mi < 4; mi++)
#pragma unroll
        for (int ni = 0; ni < 4; ni++) {
          float* c = acc[mi][ni];
          asm volatile(
            "mma.sync.aligned.m16n8k8.row.col.f32.tf32.tf32.f32 "
            "{%0,%1,%2,%3}, {%4,%5,%6,%7}, {%8,%9}, {%0,%1,%2,%3};\n"
            : "+f"(c[0]), "+f"(c[1]), "+f"(c[2]), "+f"(c[3])
            : "r"(af[mi][0]), "r"(af[mi][1]), "r"(af[mi][2]), "r"(af[mi][3]),
              "r"(bf[ni][0]), "r"(bf[ni][1]));
        }
    }
    __syncthreads();   // guards next iteration's cp.async overwrite of buffer s^1
  }

  // --- epilogue ---
#pragma unroll
  for (int mi = 0; mi < 4; mi++) {
    int row0 = rowBase + wm * 64 + mi * 16 + g;
#pragma unroll
    for (int half = 0; half < 2; half++) {
      int row = row0 + half * 8;
      float wv = 0.f;
      if (EPI == 1) wv = wgt[row * 4 + e];
#pragma unroll
      for (int ni = 0; ni < 4; ni++) {
        int col = colBase + wn * 32 + ni * 8 + 2 * t;
        float v0 = acc[mi][ni][half * 2 + 0];
        float v1 = acc[mi][ni][half * 2 + 1];
        if (EPI == 1) {
          v0 = __uint_as_float(f2tf32(gelu_tanh(v0) * wv));
          v1 = __uint_as_float(f2tf32(gelu_tanh(v1) * wv));
        }
        *(float2*)(Cp + (size_t)row * ldc + col) = make_float2(v0, v1);
      }
    }
  }
}

// ---------------------------------------------------------------------------
// Launch
// ---------------------------------------------------------------------------
extern "C" void kernel_launch(void* const* d_in, const int* in_sizes, int n_in,
                              void* d_out, int out_size) {
  const float* x  = (const float*)d_in[0];
  const float* Wg = (const float*)d_in[1];
  const float* W1 = (const float*)d_in[2];
  const float* A1 = (const float*)d_in[3];
  const float* B1 = (const float*)d_in[4];
  const float* W2 = (const float*)d_in[5];
  const float* A2 = (const float*)d_in[6];
  const float* B2 = (const float*)d_in[7];
  float* out = (float*)d_out;

  float *w1e, *w2e, *hcat, *xtf, *wgts;
  cudaGetSymbolAddress((void**)&w1e,  g_W1eff);
  cudaGetSymbolAddress((void**)&w2e,  g_W2eff);
  cudaGetSymbolAddress((void**)&hcat, g_Hcat);
  cudaGetSymbolAddress((void**)&xtf,  g_Xtf);
  cudaGetSymbolAddress((void**)&wgts, g_w);

  cudaFuncSetAttribute(gemm_tf32<0>, cudaFuncAttributeMaxDynamicSharedMemorySize, GEMM_SMEM_BYTES);
  cudaFuncSetAttribute(gemm_tf32<1>, cudaFuncAttributeMaxDynamicSharedMemorySize, GEMM_SMEM_BYTES);

  // 1) fold LoRA into effective weights (tf32-rounded)
  fold_kernel<<<NEXP * DDIM, 256>>>(W1, A1, B1, w1e, DDIM, FDIM);
  fold_kernel<<<NEXP * FDIM, 256>>>(W2, A2, B2, w2e, FDIM, DDIM);
  // 2) tf32-round activations (gating below uses raw fp32 x!)
  convert_kernel<<<(NTOK * DDIM) / (256 * 4), 256>>>(x, xtf);
  // 3) gating: top-4 selection + renormalized weights for experts 0..3
  gate_kernel<<<(NTOK * 32) / 256, 256>>>(x, Wg, wgts);
  // 4) GEMM1 (batched over 4 experts): Hcat[:, e*F:(e+1)*F] = w_e * gelu(Xtf @ W1eff[e])
  gemm_tf32<1><<<dim3(FDIM / 128, NTOK / 128, NEXP), 256, GEMM_SMEM_BYTES>>>(
      xtf, w1e, hcat, wgts,
      /*K=*/DDIM, /*lda=*/DDIM, /*ldb=*/FDIM, /*ldc=*/KCAT,
      /*Bstride=*/(long)DDIM * FDIM, /*Cstride=*/(long)FDIM);
  // 5) GEMM2: out = Hcat[8192,16384] @ W2cat[16384,1024]
  gemm_tf32<0><<<dim3(DDIM / 128, NTOK / 128, 1), 256, GEMM_SMEM_BYTES>>>(
      hcat, w2e, out, nullptr,
      /*K=*/KCAT, /*lda=*/KCAT, /*ldb=*/DDIM, /*ldc=*/DDIM,
      /*Bstride=*/0, /*Cstride=*/0);
}

// round 3
// speedup vs baseline: 3.0579x; 3.0579x over previous
#include <cuda_runtime.h>
#include <cstdint>
#include <math.h>

// Problem constants (fixed shapes for this problem instance)
#define NTOK 8192          // B*S = 2*4096 tokens
#define DDIM 1024          // model dim
#define FDIM 4096          // ffn dim
#define NEXP 4             // only experts 0..3 are referenced by the source loop

// ---------------------------------------------------------------------------
// Scratch (static device globals; allocation inside kernel_launch is banned)
// ---------------------------------------------------------------------------
__device__ float g_W1eff[(size_t)NEXP*DDIM*FDIM];   //  67 MB
__device__ float g_W2eff[(size_t)NEXP*FDIM*DDIM];   //  67 MB
__device__ float g_Hc   [(size_t)NEXP*NTOK*FDIM];   // 536 MB capacity (~1/4 used)
__device__ float g_Oc   [(size_t)NEXP*NTOK*DDIM];   // 134 MB capacity
__device__ float g_Xtf  [(size_t)NTOK*DDIM];        //  33 MB tf32-rounded activations
__device__ float g_wrow [NEXP*NTOK];                // routing weight per compacted row
__device__ int   g_list [NEXP*NTOK];                // token index per compacted row
__device__ int   g_tokloc[NTOK*4];                  // per token: up to 4 compacted locations
__device__ int   g_cnt  [NEXP];
__device__ int   g_pcnt [NEXP];                     // counts padded to 128

// ---------------------------------------------------------------------------
// Helpers
// ---------------------------------------------------------------------------
__device__ __forceinline__ uint32_t f2tf32(float f) {
  uint32_t r; asm("cvt.rna.tf32.f32 %0, %1;" : "=r"(r) : "f"(f)); return r;
}
__device__ __forceinline__ float gelu_tanh(float x) {
  float c = x + 0.044715f * x * x * x;
  return 0.5f * x * (1.0f + tanhf(0.7978845608028654f * c));
}
#define CPASYNC16(dst_u32, src_ptr) \
  asm volatile("cp.async.cg.shared.global [%0], [%1], 16;\n" :: "r"(dst_u32), "l"(src_ptr))

// ---------------------------------------------------------------------------
// Fold: out[e][row][col] = rna_tf32( W[e][row][col] + sum_r A[e][row][r]*B[e][r][col] )
// ---------------------------------------------------------------------------
__global__ void fold_kernel(const float* __restrict__ W, const float* __restrict__ A,
                            const float* __restrict__ Bm, float* __restrict__ out,
                            int rows, int cols) {
  int bid = blockIdx.x;
  int e = bid / rows, r0 = bid - e * rows;
  const float* a = A + ((size_t)e * rows + r0) * 16;
  float ar[16];
#pragma unroll
  for (int r = 0; r < 16; r++) ar[r] = a[r];
  const float* w  = W  + ((size_t)e * rows + r0) * cols;
  const float* bm = Bm + (size_t)e * 16 * cols;
  float* o = out + ((size_t)e * rows + r0) * cols;
  for (int c = threadIdx.x * 4; c < cols; c += 256 * 4) {
    float4 acc = *(const float4*)(w + c);
#pragma unroll
    for (int r = 0; r < 16; r++) {
      float4 b = *(const float4*)(bm + (size_t)r * cols + c);
      acc.x += ar[r] * b.x; acc.y += ar[r] * b.y;
      acc.z += ar[r] * b.z; acc.w += ar[r] * b.w;
    }
    float4 ov;
    ov.x = __uint_as_float(f2tf32(acc.x));
    ov.y = __uint_as_float(f2tf32(acc.y));
    ov.z = __uint_as_float(f2tf32(acc.z));
    ov.w = __uint_as_float(f2tf32(acc.w));
    *(float4*)(o + c) = ov;
  }
}

// ---------------------------------------------------------------------------
// tf32 round of activations
// ---------------------------------------------------------------------------
__global__ void convert_kernel(const float* __restrict__ x, float* __restrict__ o) {
  size_t i = ((size_t)blockIdx.x * 256 + threadIdx.x) * 4;
  float4 v = *(const float4*)(x + i);
  v.x = __uint_as_float(f2tf32(v.x));
  v.y = __uint_as_float(f2tf32(v.y));
  v.z = __uint_as_float(f2tf32(v.z));
  v.w = __uint_as_float(f2tf32(v.w));
  *(float4*)(o + i) = v;
}

__global__ void zero_cnt_kernel(int* cnt) { if (threadIdx.x < NEXP) cnt[threadIdx.x] = 0; }

// ---------------------------------------------------------------------------
// Gate v2: one warp per token. lane&15 = expert; lane>>4 selects d-half.
// Full fp32 logits from raw x (selection must match reference). Builds the
// per-expert compacted lists + per-token location table for the combine.
// ---------------------------------------------------------------------------
__global__ void gate_kernel(const float* __restrict__ x, const float* __restrict__ Wg,
                            float* __restrict__ wrow, int* __restrict__ list,
                            int* __restrict__ cnt, int* __restrict__ tokloc) {
  int wid = threadIdx.x >> 5;
  int token = blockIdx.x * (blockDim.x >> 5) + wid;
  int lane = threadIdx.x & 31;
  int laneE = lane & 15;
  int half = lane >> 4;
  const float* xr = x + (size_t)token * DDIM;
  const int dstart = half * 512;
  float acc = 0.f;
  for (int d0 = 0; d0 < 512; d0 += 16) {
    float xchunk = xr[dstart + d0 + laneE];      // 2 coalesced 64B lines / warp
#pragma unroll
    for (int k = 0; k < 16; k++) {
      float xv = __shfl_sync(0xFFFFFFFFu, xchunk, half * 16 + k);
      acc += xv * Wg[(dstart + d0 + k) * 16 + laneE];  // 2 lines / warp, L1-hot
    }
  }
  acc += __shfl_xor_sync(0xFFFFFFFFu, acc, 16);  // combine the two d-halves
  float l[16];
#pragma unroll
  for (int e = 0; e < 16; e++) l[e] = __shfl_sync(0xFFFFFFFFu, acc, e);
  if (lane == 0) {
    float mx = l[0];
#pragma unroll
    for (int e = 1; e < 16; e++) mx = fmaxf(mx, l[e]);
    float p[16];
#pragma unroll
    for (int e = 0; e < 16; e++) p[e] = expf(l[e] - mx);
    bool sel[16];
#pragma unroll
    for (int e = 0; e < 16; e++) sel[e] = false;
    float ssum = 0.f;
    for (int j = 0; j < 4; j++) {   // argmax on logits; '>' keeps lower index on ties
      int bi = 0; float bv = -3.0e38f;
      for (int e = 0; e < 16; e++)
        if (!sel[e] && l[e] > bv) { bv = l[e]; bi = e; }
      sel[bi] = true; ssum += p[bi];
    }
    float inv = 1.f / ssum;
    int slot = 0;
    for (int e = 0; e < NEXP; e++) {
      if (sel[e]) {
        int pos = atomicAdd(&cnt[e], 1);
        list[e * NTOK + pos] = token;
        wrow[e * NTOK + pos] = p[e] * inv;
        tokloc[token * 4 + slot] = e * NTOK + pos;   // ascending e -> matches ref sum order
        slot++;
      }
    }
    for (; slot < 4; slot++) tokloc[token * 4 + slot] = -1;
  }
}

// ---------------------------------------------------------------------------
// Pad counts to multiples of 128; fill padding rows with token 0 / weight 0.
// ---------------------------------------------------------------------------
__global__ void pad_kernel(const int* __restrict__ cnt, int* __restrict__ pcnt,
                           int* __restrict__ list, float* __restrict__ wrow) {
  int e = blockIdx.x;
  int c = cnt[e];
  int pc = (c + 127) & ~127;
  if (threadIdx.x == 0) pcnt[e] = pc;
  for (int i = c + threadIdx.x; i < pc; i += blockDim.x) {
    list[e * NTOK + i] = 0;
    wrow[e * NTOK + i] = 0.f;
  }
}

// ---------------------------------------------------------------------------
// tf32 GEMM: C[M,N] = A @ B. 128x128x32 tiles, 8 warps, m16n8k8 tf32 mma,
// cp.async double buffer. Early-exits row tiles beyond pcnt[e].
//   MODE 1: A rows gathered via list[e]; epilogue C = rna_tf32(gelu(acc)*wrow)
//   MODE 2: A = per-expert compacted Hc; plain fp32 store
// ---------------------------------------------------------------------------
#define SA_STRIDE 36
#define SB_STRIDE 136
#define SA_STAGE (128*SA_STRIDE)
#define SB_STAGE (32*SB_STRIDE)
#define GEMM_SMEM_BYTES ((2*SA_STAGE + 2*SB_STAGE)*4)  // 71680

template <int MODE>
__global__ void __launch_bounds__(256, 2)
gemm_tf32(const float* __restrict__ A, const float* __restrict__ Bbase,
          float* __restrict__ Cbase, const float* __restrict__ wrow,
          const int* __restrict__ list, const int* __restrict__ pcnt,
          int K, int lda, int ldb, int ldc, long Bstride, long Cstride) {
  const int e = blockIdx.z;
  const int rowBase = blockIdx.y * 128;
  if (rowBase >= pcnt[e]) return;           // uniform early exit (compaction)
  extern __shared__ float smem[];
  float* sA = smem;
  float* sB = smem + 2 * SA_STAGE;
  const int tid = threadIdx.x;
  const int lane = tid & 31, wid = tid >> 5;
  const int wm = wid >> 2, wn = wid & 3;
  const int g = lane >> 2, t = lane & 3;
  const float* Bp = Bbase + (size_t)e * Bstride;
  float* Cp = Cbase + (size_t)e * Cstride;
  const int colBase = blockIdx.x * 128;

  const uint32_t sAu = (uint32_t)__cvta_generic_to_shared(sA);
  const uint32_t sBu = (uint32_t)__cvta_generic_to_shared(sB);

  const int ar = tid >> 3, ac = (tid & 7) * 4;
  const int br = tid >> 5, bc = (tid & 31) * 4;

  // A-row source pointers (gathered for MODE 1, contiguous for MODE 2)
  const float* arow[4];
#pragma unroll
  for (int i = 0; i < 4; i++) {
    int r = rowBase + ar + i * 32;
    if (MODE == 1) {
      int tok = list[e * NTOK + r];
      arow[i] = A + (size_t)tok * lda;
    } else {
      arow[i] = A + ((size_t)e * NTOK + r) * lda;
    }
  }

  float acc[4][4][4];
#pragma unroll
  for (int i = 0; i < 4; i++)
#pragma unroll
    for (int j = 0; j < 4; j++)
#pragma unroll
      for (int k = 0; k < 4; k++) acc[i][j][k] = 0.f;

  const int KT = K >> 5;

  auto loadA = [&](int s, int kt) {
#pragma unroll
    for (int i = 0; i < 4; i++) {
      int r = ar + i * 32;
      CPASYNC16(sAu + (uint32_t)((s * SA_STAGE + r * SA_STRIDE + ac) * 4),
                arow[i] + kt * 32 + ac);
    }
  };
  auto loadB = [&](int s, int kt) {
    const float* base = Bp + (size_t)(kt * 32) * ldb + colBase;
#pragma unroll
    for (int i = 0; i < 4; i++) {
      int r = br + i * 8;
      CPASYNC16(sBu + (uint32_t)((s * SB_STAGE + r * SB_STRIDE + bc) * 4),
                base + (size_t)r * ldb + bc);
    }
  };

  loadA(0, 0); loadB(0, 0);
  asm volatile("cp.async.commit_group;\n");

  for (int kt = 0; kt < KT; ++kt) {
    int s = kt & 1;
    if (kt + 1 < KT) {
      loadA(s ^ 1, kt + 1); loadB(s ^ 1, kt + 1);
      asm volatile("cp.async.commit_group;\n");
      asm volatile("cp.async.wait_group 1;\n");
    } else {
      asm volatile("cp.async.wait_group 0;\n");
    }
    __syncthreads();
    const float* cA = sA + s * SA_STAGE;
    const float* cB = sB + s * SB_STAGE;
#pragma unroll
    for (int kk = 0; kk < 4; kk++) {
      uint32_t af[4][4], bf[4][2];
#pragma unroll
      for (int mi = 0; mi < 4; mi++) {
        const float* p = cA + (wm * 64 + mi * 16 + g) * SA_STRIDE + kk * 8 + t;
        af[mi][0] = __float_as_uint(p[0]);
        af[mi][1] = __float_as_uint(p[8 * SA_STRIDE]);
        af[mi][2] = __float_as_uint(p[4]);
        af[mi][3] = __float_as_uint(p[8 * SA_STRIDE + 4]);
      }
#pragma unroll
      for (int ni = 0; ni < 4; ni++) {
        const float* p = cB + (kk * 8 + t) * SB_STRIDE + wn * 32 + ni * 8 + g;
        bf[ni][0] = __float_as_uint(p[0]);
        bf[ni][1] = __float_as_uint(p[4 * SB_STRIDE]);
      }
#pragma unroll
      for (int mi = 0; mi < 4; mi++)
#pragma unroll
        for (int ni = 0; ni < 4; ni++) {
          float* c = acc[mi][ni];
          asm volatile(
            "mma.sync.aligned.m16n8k8.row.col.f32.tf32.tf32.f32 "
            "{%0,%1,%2,%3}, {%4,%5,%6,%7}, {%8,%9}, {%0,%1,%2,%3};\n"
            : "+f"(c[0]), "+f"(c[1]), "+f"(c[2]), "+f"(c[3])
            : "r"(af[mi][0]), "r"(af[mi][1]), "r"(af[mi][2]), "r"(af[mi][3]),
              "r"(bf[ni][0]), "r"(bf[ni][1]));
        }
    }
    __syncthreads();
  }

  // epilogue
#pragma unroll
  for (int mi = 0; mi < 4; mi++) {
    int row0 = rowBase + wm * 64 + mi * 16 + g;
#pragma unroll
    for (int half = 0; half < 2; half++) {
      int row = row0 + half * 8;
      float wv = 0.f;
      if (MODE == 1) wv = wrow[e * NTOK + row];
#pragma unroll
      for (int ni = 0; ni < 4; ni++) {
        int col = colBase + wn * 32 + ni * 8 + 2 * t;
        float v0 = acc[mi][ni][half * 2 + 0];
        float v1 = acc[mi][ni][half * 2 + 1];
        if (MODE == 1) {
          v0 = __uint_as_float(f2tf32(gelu_tanh(v0) * wv));
          v1 = __uint_as_float(f2tf32(gelu_tanh(v1) * wv));
        }
        *(float2*)(Cp + (size_t)row * ldc + col) = make_float2(v0, v1);
      }
    }
  }
}

// ---------------------------------------------------------------------------
// Combine: out[t] = sum over valid slots of Oc[loc]  (ascending expert order).
// Writes every element (also zero-fills unrouted tokens over poisoned d_out).
// ---------------------------------------------------------------------------
__global__ void combine_kernel(const float* __restrict__ Oc,
                               const int* __restrict__ tokloc,
                               float* __restrict__ out) {
  int t = blockIdx.x;
  int d = threadIdx.x * 4;
  float4 acc = make_float4(0.f, 0.f, 0.f, 0.f);
#pragma unroll
  for (int s = 0; s < 4; s++) {
    int loc = tokloc[t * 4 + s];
    if (loc >= 0) {
      float4 v = *(const float4*)(Oc + (size_t)loc * DDIM + d);
      acc.x += v.x; acc.y += v.y; acc.z += v.z; acc.w += v.w;
    }
  }
  *(float4*)(out + (size_t)t * DDIM + d) = acc;
}

// ---------------------------------------------------------------------------
// Launch
// ---------------------------------------------------------------------------
extern "C" void kernel_launch(void* const* d_in, const int* in_sizes, int n_in,
                              void* d_out, int out_size) {
  const float* x  = (const float*)d_in[0];
  const float* Wg = (const float*)d_in[1];
  const float* W1 = (const float*)d_in[2];
  const float* A1 = (const float*)d_in[3];
  const float* B1 = (const float*)d_in[4];
  const float* W2 = (const float*)d_in[5];
  const float* A2 = (const float*)d_in[6];
  const float* B2 = (const float*)d_in[7];
  float* out = (float*)d_out;

  float *w1e, *w2e, *hc, *oc, *xtf, *wrow;
  int *list, *tokloc, *cnt, *pcnt;
  cudaGetSymbolAddress((void**)&w1e,    g_W1eff);
  cudaGetSymbolAddress((void**)&w2e,    g_W2eff);
  cudaGetSymbolAddress((void**)&hc,     g_Hc);
  cudaGetSymbolAddress((void**)&oc,     g_Oc);
  cudaGetSymbolAddress((void**)&xtf,    g_Xtf);
  cudaGetSymbolAddress((void**)&wrow,   g_wrow);
  cudaGetSymbolAddress((void**)&list,   g_list);
  cudaGetSymbolAddress((void**)&tokloc, g_tokloc);
  cudaGetSymbolAddress((void**)&cnt,    g_cnt);
  cudaGetSymbolAddress((void**)&pcnt,   g_pcnt);

  cudaFuncSetAttribute(gemm_tf32<1>, cudaFuncAttributeMaxDynamicSharedMemorySize, GEMM_SMEM_BYTES);
  cudaFuncSetAttribute(gemm_tf32<2>, cudaFuncAttributeMaxDynamicSharedMemorySize, GEMM_SMEM_BYTES);

  // 0) reset routing counters
  zero_cnt_kernel<<<1, 32>>>(cnt);
  // 1) fold LoRA into effective weights (tf32-rounded)
  fold_kernel<<<NEXP * DDIM, 256>>>(W1, A1, B1, w1e, DDIM, FDIM);
  fold_kernel<<<NEXP * FDIM, 256>>>(W2, A2, B2, w2e, FDIM, DDIM);
  // 2) tf32-round activations (gating uses raw fp32 x)
  convert_kernel<<<(NTOK * DDIM) / (256 * 4), 256>>>(x, xtf);
  // 3) gating + compaction lists
  gate_kernel<<<NTOK / 8, 256>>>(x, Wg, wrow, list, cnt, tokloc);
  pad_kernel<<<NEXP, 128>>>(cnt, pcnt, list, wrow);
  // 4) GEMM1 (gathered rows): Hc[e][pos] = rna_tf32( w * gelu(X[tok] @ W1eff[e]) )
  gemm_tf32<1><<<dim3(FDIM / 128, NTOK / 128, NEXP), 256, GEMM_SMEM_BYTES>>>(
      xtf, w1e, hc, wrow, list, pcnt,
      /*K=*/DDIM, /*lda=*/DDIM, /*ldb=*/FDIM, /*ldc=*/FDIM,
      /*Bstride=*/(long)DDIM * FDIM, /*Cstride=*/(long)NTOK * FDIM);
  // 5) GEMM2 (compacted): Oc[e][pos] = Hc[e][pos] @ W2eff[e]
  gemm_tf32<2><<<dim3(DDIM / 128, NTOK / 128, NEXP), 256, GEMM_SMEM_BYTES>>>(
      hc, w2e, oc, nullptr, nullptr, pcnt,
      /*K=*/FDIM, /*lda=*/FDIM, /*ldb=*/DDIM, /*ldc=*/DDIM,
      /*Bstride=*/(long)FDIM * DDIM, /*Cstride=*/(long)NTOK * DDIM);
  // 6) scatter-combine into output (also zero-fills unrouted tokens)
  combine_kernel<<<NTOK, 256>>>(oc, tokloc, out);
}